// round 6
// baseline (speedup 1.0000x reference)
#include <cuda_runtime.h>
#include <math.h>

typedef unsigned long long ull;

#define DIMV   8192
#define NKV    8
#define NREP   8
#define HD     128
#define KVLEN  4096
#define FDV    2048
#define FEV    1024
#define EV     8
#define BV     8
#define NSPLIT 32

// ---------------- scratch ----------------
__device__ float g_an[BV * DIMV];
__device__ float g_qkv[BV * 10240];
__device__ float g_pm[BV * NKV * NSPLIT * NREP];
__device__ float g_pl[BV * NKV * NSPLIT * NREP];
__device__ float g_pacc[BV * NKV * NSPLIT * NREP * HD];
__device__ float g_attnout[BV * DIMV];
__device__ float g_h[BV * DIMV];
__device__ float g_fin[BV * DIMV];
__device__ float g_ffh1[BV * FDV];
__device__ float g_ffh3[BV * FDV];
__device__ float g_ffact[BV * FDV];
__device__ float g_expw[BV * EV];
__device__ int   g_used[EV];
__device__ float g_eh1[EV * BV * FEV];
__device__ float g_eh3[EV * BV * FEV];
__device__ float g_eact[EV * BV * FEV];

// ---------------- f32x2 helpers ----------------
__device__ __forceinline__ ull pk2(float lo, float hi) {
    ull r; asm("mov.b64 %0, {%1, %2};" : "=l"(r) : "f"(lo), "f"(hi)); return r;
}
__device__ __forceinline__ void upk2(ull v, float& lo, float& hi) {
    asm("mov.b64 {%0, %1}, %2;" : "=f"(lo), "=f"(hi) : "l"(v));
}
__device__ __forceinline__ void fma2(ull& acc, ull a, ull b) {
    asm("fma.rn.f32x2 %0, %1, %2, %0;" : "+l"(acc) : "l"(a), "l"(b));
}
__device__ __forceinline__ float gelu_exact(float x) {
    return 0.5f * x * (1.0f + erff(x * 0.70710678118654752f));
}

// ---------------- init ----------------
__global__ void k_init(const float* __restrict__ x) {
    int i = blockIdx.x * blockDim.x + threadIdx.x;
    int st = gridDim.x * blockDim.x;
    for (int j = i; j < BV * 10240; j += st) g_qkv[j] = 0.f;
    for (int j = i; j < BV * DIMV; j += st) g_h[j] = x[j];
    for (int j = i; j < BV * FDV; j += st) { g_ffh1[j] = 0.f; g_ffh3[j] = 0.f; }
    for (int j = i; j < EV * BV * FEV; j += st) { g_eh1[j] = 0.f; g_eh3[j] = 0.f; }
    if (i < EV) g_used[i] = 0;
}

// ---------------- rmsnorm ----------------
__device__ __forceinline__ void rms_core(const float* __restrict__ in,
                                         const float* __restrict__ w,
                                         float* __restrict__ outp,
                                         float* __restrict__ cpy) {
    int b = blockIdx.x;
    int t = threadIdx.x;
    const float* xr = in + b * DIMV;
    float v[16];
    float ss = 0.f;
#pragma unroll
    for (int i = 0; i < 16; i++) { v[i] = xr[t + i * 512]; ss = fmaf(v[i], v[i], ss); }
#pragma unroll
    for (int o = 16; o; o >>= 1) ss += __shfl_xor_sync(0xffffffffu, ss, o);
    __shared__ float red[16];
    __shared__ float sinv;
    if ((t & 31) == 0) red[t >> 5] = ss;
    __syncthreads();
    if (t == 0) {
        float s = 0.f;
        for (int i = 0; i < 16; i++) s += red[i];
        sinv = rsqrtf(s * (1.0f / 8192.0f) + 1e-5f);
    }
    __syncthreads();
    float inv = sinv;
#pragma unroll
    for (int i = 0; i < 16; i++) {
        int idx = t + i * 512;
        outp[b * DIMV + idx] = v[i] * inv * w[idx];
        if (cpy) cpy[b * DIMV + idx] = v[i];
    }
}
__global__ __launch_bounds__(512) void k_rms1(const float* __restrict__ x,
                                              const float* __restrict__ w) {
    rms_core(x, w, g_an, nullptr);
}
__global__ __launch_bounds__(512) void k_rms2(const float* __restrict__ w,
                                              float* __restrict__ dout) {
    rms_core(g_h, w, g_fin, dout);
}

// ---------------- KN GEMV: qkv = an @ wqkv ----------------
__global__ __launch_bounds__(256) void k_qkv(const float* __restrict__ W) {
    __shared__ float2 sx[8][256];
    int t = threadIdx.x;
    int ks = blockIdx.y * 256;
    for (int i = t; i < 8 * 256; i += 256) {
        int b = i >> 8, k = i & 255;
        float v = g_an[b * DIMV + ks + k];
        sx[b][k] = make_float2(v, v);
    }
    __syncthreads();
    int j0 = blockIdx.x * 1024 + t * 4;
    ull acc[8][2];
#pragma unroll
    for (int b = 0; b < 8; b++) { acc[b][0] = 0ULL; acc[b][1] = 0ULL; }
    const float* Wp = W + (size_t)ks * 10240 + j0;
#pragma unroll 8
    for (int d = 0; d < 256; d++) {
        float4 w4 = *(const float4*)(Wp + (size_t)d * 10240);
        ull wl = pk2(w4.x, w4.y);
        ull wh = pk2(w4.z, w4.w);
#pragma unroll
        for (int b = 0; b < 8; b++) {
            ull x2 = *(const ull*)&sx[b][d];
            fma2(acc[b][0], x2, wl);
            fma2(acc[b][1], x2, wh);
        }
    }
#pragma unroll
    for (int b = 0; b < 8; b++) {
        float lo, hi;
        upk2(acc[b][0], lo, hi);
        atomicAdd(g_qkv + b * 10240 + j0 + 0, lo);
        atomicAdd(g_qkv + b * 10240 + j0 + 1, hi);
        upk2(acc[b][1], lo, hi);
        atomicAdd(g_qkv + b * 10240 + j0 + 2, lo);
        atomicAdd(g_qkv + b * 10240 + j0 + 3, hi);
    }
}

// ---------------- attention partials (RoPE fused, flash decoding) ----------------
__global__ __launch_bounds__(256) void k_attn(const float* __restrict__ ck,
                                              const float* __restrict__ cv,
                                              const float* __restrict__ mask,
                                              const float* __restrict__ cosn,
                                              const float* __restrict__ sinn,
                                              const int* __restrict__ spp) {
    int split = blockIdx.x, kvh = blockIdx.y, b = blockIdx.z;
    int warp = threadIdx.x >> 5, lane = threadIdx.x & 31;
    int sp = *spp;
    // rope coefficients for this lane's 2 pairs
    float c0 = cosn[lane * 2], s0 = sinn[lane * 2];
    float c1 = cosn[lane * 2 + 1], s1 = sinn[lane * 2 + 1];
    // q with rope applied on the fly
    const float* qkvb = g_qkv + b * 10240 + kvh * 1280;
    float4 qr = *(const float4*)(qkvb + warp * 128 + lane * 4);
    float4 q;
    q.x = qr.x * c0 - qr.y * s0; q.y = qr.x * s0 + qr.y * c0;
    q.z = qr.z * c1 - qr.w * s1; q.w = qr.z * s1 + qr.w * c1;
    // new-position k (roped) and v
    float4 nkr = *(const float4*)(qkvb + 1024 + lane * 4);
    float4 nk;
    nk.x = nkr.x * c0 - nkr.y * s0; nk.y = nkr.x * s0 + nkr.y * c0;
    nk.z = nkr.z * c1 - nkr.w * s1; nk.w = nkr.z * s1 + nkr.w * c1;
    float4 nv = *(const float4*)(qkvb + 1152 + lane * 4);

    float m = -1e30f, l = 0.f;
    float4 acc = make_float4(0.f, 0.f, 0.f, 0.f);
    int p0 = split * (KVLEN / NSPLIT);
    const float scale = 0.08838834764831845f;
    for (int pp = 0; pp < KVLEN / NSPLIT; pp += 4) {
        float d[4];
        float4 v4[4];
        float mk[4];
#pragma unroll
        for (int u = 0; u < 4; u++) {
            int pos = p0 + pp + u;
            size_t coff = (((size_t)b * KVLEN + pos) * NKV + kvh) * HD + lane * 4;
            float4 k4 = *(const float4*)(ck + coff);
            v4[u] = *(const float4*)(cv + coff);
            if (pos == sp) { k4 = nk; v4[u] = nv; }
            mk[u] = mask[pos];
            d[u] = q.x * k4.x + q.y * k4.y + q.z * k4.z + q.w * k4.w;
        }
#pragma unroll
        for (int o = 16; o; o >>= 1) {
#pragma unroll
            for (int u = 0; u < 4; u++) d[u] += __shfl_xor_sync(0xffffffffu, d[u], o);
        }
        float s0v = d[0] * scale + mk[0];
        float s1v = d[1] * scale + mk[1];
        float s2v = d[2] * scale + mk[2];
        float s3v = d[3] * scale + mk[3];
        float mn = fmaxf(fmaxf(fmaxf(s0v, s1v), fmaxf(s2v, s3v)), m);
        float c  = __expf(m - mn);
        float e0 = __expf(s0v - mn), e1 = __expf(s1v - mn);
        float e2 = __expf(s2v - mn), e3 = __expf(s3v - mn);
        m = mn;
        l = l * c + (e0 + e1) + (e2 + e3);
        acc.x = fmaf(acc.x, c, e0 * v4[0].x + e1 * v4[1].x + e2 * v4[2].x + e3 * v4[3].x);
        acc.y = fmaf(acc.y, c, e0 * v4[0].y + e1 * v4[1].y + e2 * v4[2].y + e3 * v4[3].y);
        acc.z = fmaf(acc.z, c, e0 * v4[0].z + e1 * v4[1].z + e2 * v4[2].z + e3 * v4[3].z);
        acc.w = fmaf(acc.w, c, e0 * v4[0].w + e1 * v4[1].w + e2 * v4[2].w + e3 * v4[3].w);
    }
    int idx = ((b * 8 + kvh) * NSPLIT + split) * NREP + warp;
    if (lane == 0) { g_pm[idx] = m; g_pl[idx] = l; }
    *(float4*)(g_pacc + (size_t)idx * HD + lane * 4) = acc;
}

// ---------------- combine ----------------
__global__ __launch_bounds__(256) void k_comb() {
    int bk = blockIdx.x;
    int b = bk >> 3, kvh = bk & 7;
    int warp = threadIdx.x >> 5, lane = threadIdx.x & 31;
    int base = ((b * 8 + kvh) * NSPLIT) * NREP + warp;
    float mg = -1e30f;
    for (int s = 0; s < NSPLIT; s++) mg = fmaxf(mg, g_pm[base + s * NREP]);
    float lg = 0.f;
    float4 a = make_float4(0.f, 0.f, 0.f, 0.f);
    for (int s = 0; s < NSPLIT; s++) {
        int idx = base + s * NREP;
        float c = __expf(g_pm[idx] - mg);
        lg += g_pl[idx] * c;
        float4 pa = *(const float4*)(g_pacc + (size_t)idx * HD + lane * 4);
        a.x += c * pa.x; a.y += c * pa.y; a.z += c * pa.z; a.w += c * pa.w;
    }
    float inv = 1.0f / lg;
    float* dst = g_attnout + (size_t)b * DIMV + (kvh * 8 + warp) * HD + lane * 4;
    *(float4*)dst = make_float4(a.x * inv, a.y * inv, a.z * inv, a.w * inv);
}

// ---------------- NK GEMV: 4 rows/warp, transient x regs, batched LDGs ----------------
__device__ __forceinline__ void gemv_nk(const float* __restrict__ X,
                                        const float* __restrict__ W,
                                        float* __restrict__ Y,
                                        int N, int K, int n_tile, int k0, int kc_len) {
    __shared__ float sx[8][1024];
    const int lane = threadIdx.x & 31;
    const int warp = threadIdx.x >> 5;
    const int n0 = n_tile * 32 + warp * 4;
    const int lane4 = lane * 4;

    const float* Wr0 = W + (size_t)(n0 + 0) * K;
    const float* Wr1 = W + (size_t)(n0 + 1) * K;
    const float* Wr2 = W + (size_t)(n0 + 2) * K;
    const float* Wr3 = W + (size_t)(n0 + 3) * K;

    ull acc[4][8];
#pragma unroll
    for (int r = 0; r < 4; r++)
#pragma unroll
        for (int b = 0; b < 8; b++) acc[r][b] = 0ULL;

    for (int ks = k0; ks < k0 + kc_len; ks += 1024) {
        __syncthreads();
#pragma unroll
        for (int i = threadIdx.x; i < 2048; i += 256) {
            int b = i >> 8, kq = i & 255;
            *(float4*)&sx[b][kq * 4] = *(const float4*)(X + (size_t)b * K + ks + kq * 4);
        }
        __syncthreads();
#pragma unroll 2
        for (int kk = lane4; kk < 1024; kk += 128) {
            float4 w0 = *(const float4*)(Wr0 + ks + kk);
            float4 w1 = *(const float4*)(Wr1 + ks + kk);
            float4 w2 = *(const float4*)(Wr2 + ks + kk);
            float4 w3 = *(const float4*)(Wr3 + ks + kk);
            ull wl0 = pk2(w0.x, w0.y), wh0 = pk2(w0.z, w0.w);
            ull wl1 = pk2(w1.x, w1.y), wh1 = pk2(w1.z, w1.w);
            ull wl2 = pk2(w2.x, w2.y), wh2 = pk2(w2.z, w2.w);
            ull wl3 = pk2(w3.x, w3.y), wh3 = pk2(w3.z, w3.w);
#pragma unroll
            for (int b = 0; b < 8; b++) {
                ulonglong2 xv = *(const ulonglong2*)&sx[b][kk];
                fma2(acc[0][b], wl0, xv.x); fma2(acc[0][b], wh0, xv.y);
                fma2(acc[1][b], wl1, xv.x); fma2(acc[1][b], wh1, xv.y);
                fma2(acc[2][b], wl2, xv.x); fma2(acc[2][b], wh2, xv.y);
                fma2(acc[3][b], wl3, xv.x); fma2(acc[3][b], wh3, xv.y);
            }
        }
    }
#pragma unroll
    for (int r = 0; r < 4; r++) {
#pragma unroll
        for (int b = 0; b < 8; b++) {
            float lo, hi;
            upk2(acc[r][b], lo, hi);
            float v = lo + hi;
#pragma unroll
            for (int o = 16; o; o >>= 1) v += __shfl_down_sync(0xffffffffu, v, o);
            if (lane == 0) atomicAdd(Y + (size_t)b * N + n0 + r, v);
        }
    }
}

__global__ __launch_bounds__(256, 2) void k_wo(const float* __restrict__ W) {
    gemv_nk(g_attnout, W, g_h, DIMV, DIMV, blockIdx.x, blockIdx.y * 2048, 2048);
}

// fused: moe13 (1024 blocks) + dense ffn13 (256 blocks)
__global__ __launch_bounds__(256, 2) void k_fused13(const float* __restrict__ w1,
                                                    const float* __restrict__ w3,
                                                    const float* __restrict__ m1,
                                                    const float* __restrict__ m3) {
    int id = blockIdx.x;
    if (id < 1024) {
        int e = id >> 7;
        if (!g_used[e]) return;
        int r = id & 127;
        int w13 = r & 1;
        int ksp = (r >> 1) & 1;
        int tile = r >> 2;                  // 0..31
        const float* W = (w13 ? m3 : m1) + (size_t)e * FEV * DIMV;
        float* Y = (w13 ? g_eh3 : g_eh1) + e * BV * FEV;
        gemv_nk(g_fin, W, Y, FEV, DIMV, tile, ksp * 4096, 4096);
    } else {
        int r = id - 1024;
        int w13 = r & 1;
        int ksp = (r >> 1) & 1;
        int tile = r >> 2;                  // 0..63
        gemv_nk(g_fin, (w13 ? w3 : w1), (w13 ? g_ffh3 : g_ffh1), FDV, DIMV,
                tile, ksp * 4096, 4096);
    }
}

// fused: moe2 (2048 blocks) + dense ffn2 (256 blocks)
__global__ __launch_bounds__(256, 2) void k_fused2(const float* __restrict__ w2,
                                                   const float* __restrict__ m2,
                                                   float* __restrict__ out) {
    int id = blockIdx.x;
    if (id < 2048) {
        int e = id >> 8;
        if (!g_used[e]) return;
        int tile = id & 255;
        gemv_nk(g_eact + e * BV * FEV, m2 + (size_t)e * DIMV * FEV, out,
                DIMV, FEV, tile, 0, FEV);
    } else {
        int tile = id - 2048;               // 0..255
        gemv_nk(g_ffact, w2, out, DIMV, FDV, tile, 0, FDV);
    }
}

// ---------------- gating ----------------
__global__ __launch_bounds__(256) void k_gate(const float* __restrict__ gw) {
    int b = blockIdx.x;
    int warp = threadIdx.x >> 5, lane = threadIdx.x & 31;
    __shared__ float lg[EV];
    const float* x = g_fin + b * DIMV;
    const float* w = gw + warp * DIMV;
    float s = 0.f;
    for (int k = lane * 4; k < DIMV; k += 128) {
        float4 xv = *(const float4*)(x + k);
        float4 wv = *(const float4*)(w + k);
        s += xv.x * wv.x + xv.y * wv.y + xv.z * wv.z + xv.w * wv.w;
    }
#pragma unroll
    for (int o = 16; o; o >>= 1) s += __shfl_xor_sync(0xffffffffu, s, o);
    if (lane == 0) lg[warp] = s;
    __syncthreads();
    if (threadIdx.x == 0) {
        float mx = -1e30f;
        for (int e = 0; e < EV; e++) mx = fmaxf(mx, lg[e]);
        float p[EV], sum = 0.f;
        for (int e = 0; e < EV; e++) { p[e] = __expf(lg[e] - mx); sum += p[e]; }
        for (int e = 0; e < EV; e++) p[e] /= sum;
        int i1 = 0;
        for (int e = 1; e < EV; e++) if (p[e] > p[i1]) i1 = e;
        int i2 = -1;
        for (int e = 0; e < EV; e++) if (e != i1 && (i2 < 0 || p[e] > p[i2])) i2 = e;
        for (int e = 0; e < EV; e++) g_expw[b * EV + e] = 0.f;
        g_expw[b * EV + i1] = p[i1];
        g_expw[b * EV + i2] = p[i2];
        atomicOr(&g_used[i1], 1);
        atomicOr(&g_used[i2], 1);
    }
}

// ---------------- fused activations ----------------
__global__ void k_act() {
    int i = blockIdx.x * 256 + threadIdx.x;
    if (i < BV * FDV) {
        g_ffact[i] = gelu_exact(g_ffh1[i]) * g_ffh3[i];
    } else {
        int j = i - BV * FDV;
        if (j < EV * BV * FEV) {
            int e = j >> 13;
            int b = (j >> 10) & 7;
            g_eact[j] = gelu_exact(g_eh1[j]) * g_eh3[j] * g_expw[b * EV + e];
        }
    }
}

// ---------------- launch ----------------
extern "C" void kernel_launch(void* const* d_in, const int* in_sizes, int n_in,
                              void* d_out, int out_size) {
    const float* x    = (const float*)d_in[0];
    const float* mask = (const float*)d_in[1];
    const float* fc   = (const float*)d_in[2];
    const float* fs   = (const float*)d_in[3];
    const float* ck   = (const float*)d_in[4];
    const float* cv   = (const float*)d_in[5];
    const float* wqkv = (const float*)d_in[6];
    const float* wo   = (const float*)d_in[7];
    const float* anw  = (const float*)d_in[8];
    const float* fnw  = (const float*)d_in[9];
    const float* w1   = (const float*)d_in[10];
    const float* w2   = (const float*)d_in[11];
    const float* w3   = (const float*)d_in[12];
    const float* gw   = (const float*)d_in[13];
    const float* m1   = (const float*)d_in[14];
    const float* m2   = (const float*)d_in[15];
    const float* m3   = (const float*)d_in[16];
    const int*   sp   = (const int*)d_in[17];
    float* out = (float*)d_out;

    k_init<<<148, 256>>>(x);                            // 1
    k_rms1<<<8, 512>>>(x, anw);                         // 2
    k_qkv<<<dim3(10, 32), 256>>>(wqkv);                 // 3
    k_attn<<<dim3(NSPLIT, NKV, BV), 256>>>(ck, cv, mask, fc, fs, sp);  // 4
    k_comb<<<64, 256>>>();                              // 5
    k_wo<<<dim3(256, 4), 256>>>(wo);                    // 6  <- ncu -s 5 capture target
    k_rms2<<<8, 512>>>(fnw, out);                       // 7
    k_gate<<<8, 256>>>(gw);                             // 8
    k_fused13<<<1280, 256>>>(w1, w3, m1, m3);           // 9
    k_act<<<(BV * FDV + EV * BV * FEV + 255) / 256, 256>>>();  // 10
    k_fused2<<<2304, 256>>>(w2, m2, out);               // 11
}

// round 7
// speedup vs baseline: 1.2133x; 1.2133x over previous
#include <cuda_runtime.h>
#include <math.h>

typedef unsigned long long ull;

#define DIMV   8192
#define NKV    8
#define NREP   8
#define HD     128
#define KVLEN  4096
#define FDV    2048
#define FEV    1024
#define EV     8
#define BV     8
#define NSPLIT 32

// ---------------- scratch ----------------
__device__ float g_an[BV * DIMV];
__device__ float g_qkv[BV * 10240];
__device__ float g_pm[BV * NKV * NSPLIT * NREP];
__device__ float g_pl[BV * NKV * NSPLIT * NREP];
__device__ float g_pacc[BV * NKV * NSPLIT * NREP * HD];
__device__ float g_attnout[BV * DIMV];
__device__ float g_h[BV * DIMV];
__device__ float g_fin[BV * DIMV];
__device__ float g_ffh1[BV * FDV];
__device__ float g_ffh3[BV * FDV];
__device__ float g_ffact[BV * FDV];
__device__ float g_expw[BV * EV];
__device__ int   g_used[EV];
__device__ float g_eh1[EV * BV * FEV];
__device__ float g_eh3[EV * BV * FEV];
__device__ float g_eact[EV * BV * FEV];

// ---------------- f32x2 helpers ----------------
__device__ __forceinline__ ull pk2(float lo, float hi) {
    ull r; asm("mov.b64 %0, {%1, %2};" : "=l"(r) : "f"(lo), "f"(hi)); return r;
}
__device__ __forceinline__ void upk2(ull v, float& lo, float& hi) {
    asm("mov.b64 {%0, %1}, %2;" : "=f"(lo), "=f"(hi) : "l"(v));
}
__device__ __forceinline__ void fma2(ull& acc, ull a, ull b) {
    asm("fma.rn.f32x2 %0, %1, %2, %0;" : "+l"(acc) : "l"(a), "l"(b));
}
__device__ __forceinline__ float gelu_exact(float x) {
    return 0.5f * x * (1.0f + erff(x * 0.70710678118654752f));
}

// ---------------- init ----------------
__global__ void k_init(const float* __restrict__ x) {
    int i = blockIdx.x * blockDim.x + threadIdx.x;
    int st = gridDim.x * blockDim.x;
    for (int j = i; j < BV * 10240; j += st) g_qkv[j] = 0.f;
    for (int j = i; j < BV * DIMV; j += st) g_h[j] = x[j];
    for (int j = i; j < BV * FDV; j += st) { g_ffh1[j] = 0.f; g_ffh3[j] = 0.f; }
    for (int j = i; j < EV * BV * FEV; j += st) { g_eh1[j] = 0.f; g_eh3[j] = 0.f; }
    if (i < EV) g_used[i] = 0;
}

// ---------------- rmsnorm ----------------
__device__ __forceinline__ void rms_core(const float* __restrict__ in,
                                         const float* __restrict__ w,
                                         float* __restrict__ outp,
                                         float* __restrict__ cpy) {
    int b = blockIdx.x;
    int t = threadIdx.x;
    const float* xr = in + b * DIMV;
    float v[16];
    float ss = 0.f;
#pragma unroll
    for (int i = 0; i < 16; i++) { v[i] = xr[t + i * 512]; ss = fmaf(v[i], v[i], ss); }
#pragma unroll
    for (int o = 16; o; o >>= 1) ss += __shfl_xor_sync(0xffffffffu, ss, o);
    __shared__ float red[16];
    __shared__ float sinv;
    if ((t & 31) == 0) red[t >> 5] = ss;
    __syncthreads();
    if (t == 0) {
        float s = 0.f;
        for (int i = 0; i < 16; i++) s += red[i];
        sinv = rsqrtf(s * (1.0f / 8192.0f) + 1e-5f);
    }
    __syncthreads();
    float inv = sinv;
#pragma unroll
    for (int i = 0; i < 16; i++) {
        int idx = t + i * 512;
        outp[b * DIMV + idx] = v[i] * inv * w[idx];
        if (cpy) cpy[b * DIMV + idx] = v[i];
    }
}
__global__ __launch_bounds__(512) void k_rms1(const float* __restrict__ x,
                                              const float* __restrict__ w) {
    rms_core(x, w, g_an, nullptr);
}
__global__ __launch_bounds__(512) void k_rms2(const float* __restrict__ w,
                                              float* __restrict__ dout) {
    rms_core(g_h, w, g_fin, dout);
}

// ---------------- KN GEMV: qkv = an @ wqkv ----------------
__global__ __launch_bounds__(256) void k_qkv(const float* __restrict__ W) {
    __shared__ float2 sx[8][256];
    int t = threadIdx.x;
    int ks = blockIdx.y * 256;
    for (int i = t; i < 8 * 256; i += 256) {
        int b = i >> 8, k = i & 255;
        float v = g_an[b * DIMV + ks + k];
        sx[b][k] = make_float2(v, v);
    }
    __syncthreads();
    int j0 = blockIdx.x * 1024 + t * 4;
    ull acc[8][2];
#pragma unroll
    for (int b = 0; b < 8; b++) { acc[b][0] = 0ULL; acc[b][1] = 0ULL; }
    const float* Wp = W + (size_t)ks * 10240 + j0;
#pragma unroll 8
    for (int d = 0; d < 256; d++) {
        float4 w4 = *(const float4*)(Wp + (size_t)d * 10240);
        ull wl = pk2(w4.x, w4.y);
        ull wh = pk2(w4.z, w4.w);
#pragma unroll
        for (int b = 0; b < 8; b++) {
            ull x2 = *(const ull*)&sx[b][d];
            fma2(acc[b][0], x2, wl);
            fma2(acc[b][1], x2, wh);
        }
    }
#pragma unroll
    for (int b = 0; b < 8; b++) {
        float lo, hi;
        upk2(acc[b][0], lo, hi);
        atomicAdd(g_qkv + b * 10240 + j0 + 0, lo);
        atomicAdd(g_qkv + b * 10240 + j0 + 1, hi);
        upk2(acc[b][1], lo, hi);
        atomicAdd(g_qkv + b * 10240 + j0 + 2, lo);
        atomicAdd(g_qkv + b * 10240 + j0 + 3, hi);
    }
}

// ---------------- attention: smem-staged flash decoding ----------------
// grid (32 splits, 8 kvh, 8 b), 256 thr = 8 warps = 8 q-heads.
// Tile 32 positions staged to shared once per block; lane = position for scores.
__global__ __launch_bounds__(256) void k_attn(const float* __restrict__ ck,
                                              const float* __restrict__ cv,
                                              const float* __restrict__ mask,
                                              const float* __restrict__ cosn,
                                              const float* __restrict__ sinn,
                                              const int* __restrict__ spp) {
    __shared__ float qs[8][128];
    __shared__ float ks[32][130];        // stride 130: 2-way max conflict on f32x2
    __shared__ float vs[32][132];        // stride 132: aligned LDS.128, conflict-free
    __shared__ float mks[32];
    __shared__ float snk[128], snv[128];

    int split = blockIdx.x, kvh = blockIdx.y, b = blockIdx.z;
    int warp = threadIdx.x >> 5, lane = threadIdx.x & 31;
    int sp = *spp;
    const float* qkvb = g_qkv + b * 10240 + kvh * 1280;

    // rope coefficients for this lane's 2 pairs (dims lane*4 .. lane*4+3)
    float c0 = cosn[lane * 2], s0 = sinn[lane * 2];
    float c1 = cosn[lane * 2 + 1], s1 = sinn[lane * 2 + 1];

    // per-warp q (roped) -> qs
    {
        float4 qr = *(const float4*)(qkvb + warp * 128 + lane * 4);
        float4 q;
        q.x = qr.x * c0 - qr.y * s0; q.y = qr.x * s0 + qr.y * c0;
        q.z = qr.z * c1 - qr.w * s1; q.w = qr.z * s1 + qr.w * c1;
        *(float4*)&qs[warp][lane * 4] = q;
    }
    // new-position roped k and raw v
    if (warp == 0) {
        float4 nkr = *(const float4*)(qkvb + 1024 + lane * 4);
        float4 nk;
        nk.x = nkr.x * c0 - nkr.y * s0; nk.y = nkr.x * s0 + nkr.y * c0;
        nk.z = nkr.z * c1 - nkr.w * s1; nk.w = nkr.z * s1 + nkr.w * c1;
        *(float4*)&snk[lane * 4] = nk;
        *(float4*)&snv[lane * 4] = *(const float4*)(qkvb + 1152 + lane * 4);
    }

    float m = -1e30f, l = 0.f;
    float4 acc = make_float4(0.f, 0.f, 0.f, 0.f);
    const float scale = 0.08838834764831845f;
    int p0 = split * 128;

    for (int tile = 0; tile < 4; tile++) {
        int base = p0 + tile * 32;
        __syncthreads();
        // stage K/V tile (each warp stages 4 rows of each)
#pragma unroll
        for (int i = threadIdx.x; i < 1024; i += 256) {
            int p = i >> 5, dc = i & 31;
            int pos = base + p;
            size_t coff = (((size_t)b * KVLEN + pos) * NKV + kvh) * HD + dc * 4;
            float4 kk = *(const float4*)(ck + coff);
            float4 vv = *(const float4*)(cv + coff);
            if (pos == sp) {
                kk = *(const float4*)&snk[dc * 4];
                vv = *(const float4*)&snv[dc * 4];
            }
            ks[p][dc * 4 + 0] = kk.x; ks[p][dc * 4 + 1] = kk.y;
            ks[p][dc * 4 + 2] = kk.z; ks[p][dc * 4 + 3] = kk.w;
            *(float4*)&vs[p][dc * 4] = vv;
        }
        if (threadIdx.x < 32) mks[threadIdx.x] = mask[base + threadIdx.x];
        __syncthreads();

        // ---- scores: lane = position ----
        ull a0 = 0ULL, a1 = 0ULL, a2 = 0ULL, a3 = 0ULL;
        const float* kr = &ks[lane][0];
        const float* qr = &qs[warp][0];
#pragma unroll
        for (int d = 0; d < 128; d += 8) {
            fma2(a0, *(const ull*)(kr + d),     *(const ull*)(qr + d));
            fma2(a1, *(const ull*)(kr + d + 2), *(const ull*)(qr + d + 2));
            fma2(a2, *(const ull*)(kr + d + 4), *(const ull*)(qr + d + 4));
            fma2(a3, *(const ull*)(kr + d + 6), *(const ull*)(qr + d + 6));
        }
        float lo, hi, s;
        upk2(a0, lo, hi); s = lo + hi;
        upk2(a1, lo, hi); s += lo + hi;
        upk2(a2, lo, hi); s += lo + hi;
        upk2(a3, lo, hi); s += lo + hi;
        s = s * scale + mks[lane];

        // ---- warp softmax over the 32 positions ----
        float tm = s;
#pragma unroll
        for (int o = 16; o; o >>= 1) tm = fmaxf(tm, __shfl_xor_sync(0xffffffffu, tm, o));
        float mn = fmaxf(m, tm);
        float c = __expf(m - mn);
        float p = __expf(s - mn);
        m = mn;
        float tl = p;
#pragma unroll
        for (int o = 16; o; o >>= 1) tl += __shfl_xor_sync(0xffffffffu, tl, o);
        l = l * c + tl;
        acc.x *= c; acc.y *= c; acc.z *= c; acc.w *= c;

        // ---- V accumulation: lane owns dims lane*4..+3 ----
#pragma unroll
        for (int q4 = 0; q4 < 32; q4 += 4) {
            float pa = __shfl_sync(0xffffffffu, p, q4 + 0);
            float pb = __shfl_sync(0xffffffffu, p, q4 + 1);
            float pc = __shfl_sync(0xffffffffu, p, q4 + 2);
            float pd = __shfl_sync(0xffffffffu, p, q4 + 3);
            float4 va = *(const float4*)&vs[q4 + 0][lane * 4];
            float4 vb = *(const float4*)&vs[q4 + 1][lane * 4];
            float4 vc = *(const float4*)&vs[q4 + 2][lane * 4];
            float4 vd = *(const float4*)&vs[q4 + 3][lane * 4];
            acc.x += pa * va.x + pb * vb.x + pc * vc.x + pd * vd.x;
            acc.y += pa * va.y + pb * vb.y + pc * vc.y + pd * vd.y;
            acc.z += pa * va.z + pb * vb.z + pc * vc.z + pd * vd.z;
            acc.w += pa * va.w + pb * vb.w + pc * vc.w + pd * vd.w;
        }
    }

    int idx = ((b * 8 + kvh) * NSPLIT + split) * NREP + warp;
    if (lane == 0) { g_pm[idx] = m; g_pl[idx] = l; }
    *(float4*)(g_pacc + (size_t)idx * HD + lane * 4) = acc;
}

// ---------------- combine ----------------
__global__ __launch_bounds__(256) void k_comb() {
    int bk = blockIdx.x;
    int b = bk >> 3, kvh = bk & 7;
    int warp = threadIdx.x >> 5, lane = threadIdx.x & 31;
    int base = ((b * 8 + kvh) * NSPLIT) * NREP + warp;
    float mg = -1e30f;
    for (int s = 0; s < NSPLIT; s++) mg = fmaxf(mg, g_pm[base + s * NREP]);
    float lg = 0.f;
    float4 a = make_float4(0.f, 0.f, 0.f, 0.f);
    for (int s = 0; s < NSPLIT; s++) {
        int idx = base + s * NREP;
        float c = __expf(g_pm[idx] - mg);
        lg += g_pl[idx] * c;
        float4 pa = *(const float4*)(g_pacc + (size_t)idx * HD + lane * 4);
        a.x += c * pa.x; a.y += c * pa.y; a.z += c * pa.z; a.w += c * pa.w;
    }
    float inv = 1.0f / lg;
    float* dst = g_attnout + (size_t)b * DIMV + (kvh * 8 + warp) * HD + lane * 4;
    *(float4*)dst = make_float4(a.x * inv, a.y * inv, a.z * inv, a.w * inv);
}

// ---------------- NK GEMV ----------------
__device__ __forceinline__ void gemv_nk(const float* __restrict__ X,
                                        const float* __restrict__ W,
                                        float* __restrict__ Y,
                                        int N, int K, int n_tile, int k0, int kc_len) {
    __shared__ float sx[8][1024];
    const int lane = threadIdx.x & 31;
    const int warp = threadIdx.x >> 5;
    const int n0 = n_tile * 32 + warp * 4;
    const int lane4 = lane * 4;

    const float* Wr0 = W + (size_t)(n0 + 0) * K;
    const float* Wr1 = W + (size_t)(n0 + 1) * K;
    const float* Wr2 = W + (size_t)(n0 + 2) * K;
    const float* Wr3 = W + (size_t)(n0 + 3) * K;

    ull acc[4][8];
#pragma unroll
    for (int r = 0; r < 4; r++)
#pragma unroll
        for (int b = 0; b < 8; b++) acc[r][b] = 0ULL;

    for (int ks = k0; ks < k0 + kc_len; ks += 1024) {
        __syncthreads();
#pragma unroll
        for (int i = threadIdx.x; i < 2048; i += 256) {
            int b = i >> 8, kq = i & 255;
            *(float4*)&sx[b][kq * 4] = *(const float4*)(X + (size_t)b * K + ks + kq * 4);
        }
        __syncthreads();
#pragma unroll 2
        for (int kk = lane4; kk < 1024; kk += 128) {
            float4 w0 = *(const float4*)(Wr0 + ks + kk);
            float4 w1 = *(const float4*)(Wr1 + ks + kk);
            float4 w2 = *(const float4*)(Wr2 + ks + kk);
            float4 w3 = *(const float4*)(Wr3 + ks + kk);
            ull wl0 = pk2(w0.x, w0.y), wh0 = pk2(w0.z, w0.w);
            ull wl1 = pk2(w1.x, w1.y), wh1 = pk2(w1.z, w1.w);
            ull wl2 = pk2(w2.x, w2.y), wh2 = pk2(w2.z, w2.w);
            ull wl3 = pk2(w3.x, w3.y), wh3 = pk2(w3.z, w3.w);
#pragma unroll
            for (int b = 0; b < 8; b++) {
                ulonglong2 xv = *(const ulonglong2*)&sx[b][kk];
                fma2(acc[0][b], wl0, xv.x); fma2(acc[0][b], wh0, xv.y);
                fma2(acc[1][b], wl1, xv.x); fma2(acc[1][b], wh1, xv.y);
                fma2(acc[2][b], wl2, xv.x); fma2(acc[2][b], wh2, xv.y);
                fma2(acc[3][b], wl3, xv.x); fma2(acc[3][b], wh3, xv.y);
            }
        }
    }
#pragma unroll
    for (int r = 0; r < 4; r++) {
#pragma unroll
        for (int b = 0; b < 8; b++) {
            float lo, hi;
            upk2(acc[r][b], lo, hi);
            float v = lo + hi;
#pragma unroll
            for (int o = 16; o; o >>= 1) v += __shfl_down_sync(0xffffffffu, v, o);
            if (lane == 0) atomicAdd(Y + (size_t)b * N + n0 + r, v);
        }
    }
}

__global__ __launch_bounds__(256, 2) void k_wo(const float* __restrict__ W) {
    gemv_nk(g_attnout, W, g_h, DIMV, DIMV, blockIdx.x, blockIdx.y * 2048, 2048);
}

__global__ __launch_bounds__(256, 2) void k_fused13(const float* __restrict__ w1,
                                                    const float* __restrict__ w3,
                                                    const float* __restrict__ m1,
                                                    const float* __restrict__ m3) {
    int id = blockIdx.x;
    if (id < 1024) {
        int e = id >> 7;
        if (!g_used[e]) return;
        int r = id & 127;
        int w13 = r & 1;
        int ksp = (r >> 1) & 1;
        int tile = r >> 2;
        const float* W = (w13 ? m3 : m1) + (size_t)e * FEV * DIMV;
        float* Y = (w13 ? g_eh3 : g_eh1) + e * BV * FEV;
        gemv_nk(g_fin, W, Y, FEV, DIMV, tile, ksp * 4096, 4096);
    } else {
        int r = id - 1024;
        int w13 = r & 1;
        int ksp = (r >> 1) & 1;
        int tile = r >> 2;
        gemv_nk(g_fin, (w13 ? w3 : w1), (w13 ? g_ffh3 : g_ffh1), FDV, DIMV,
                tile, ksp * 4096, 4096);
    }
}

__global__ __launch_bounds__(256, 2) void k_fused2(const float* __restrict__ w2,
                                                   const float* __restrict__ m2,
                                                   float* __restrict__ out) {
    int id = blockIdx.x;
    if (id < 2048) {
        int e = id >> 8;
        if (!g_used[e]) return;
        int tile = id & 255;
        gemv_nk(g_eact + e * BV * FEV, m2 + (size_t)e * DIMV * FEV, out,
                DIMV, FEV, tile, 0, FEV);
    } else {
        int tile = id - 2048;
        gemv_nk(g_ffact, w2, out, DIMV, FDV, tile, 0, FDV);
    }
}

// ---------------- gating ----------------
__global__ __launch_bounds__(256) void k_gate(const float* __restrict__ gw) {
    int b = blockIdx.x;
    int warp = threadIdx.x >> 5, lane = threadIdx.x & 31;
    __shared__ float lg[EV];
    const float* x = g_fin + b * DIMV;
    const float* w = gw + warp * DIMV;
    float s = 0.f;
    for (int k = lane * 4; k < DIMV; k += 128) {
        float4 xv = *(const float4*)(x + k);
        float4 wv = *(const float4*)(w + k);
        s += xv.x * wv.x + xv.y * wv.y + xv.z * wv.z + xv.w * wv.w;
    }
#pragma unroll
    for (int o = 16; o; o >>= 1) s += __shfl_xor_sync(0xffffffffu, s, o);
    if (lane == 0) lg[warp] = s;
    __syncthreads();
    if (threadIdx.x == 0) {
        float mx = -1e30f;
        for (int e = 0; e < EV; e++) mx = fmaxf(mx, lg[e]);
        float p[EV], sum = 0.f;
        for (int e = 0; e < EV; e++) { p[e] = __expf(lg[e] - mx); sum += p[e]; }
        for (int e = 0; e < EV; e++) p[e] /= sum;
        int i1 = 0;
        for (int e = 1; e < EV; e++) if (p[e] > p[i1]) i1 = e;
        int i2 = -1;
        for (int e = 0; e < EV; e++) if (e != i1 && (i2 < 0 || p[e] > p[i2])) i2 = e;
        for (int e = 0; e < EV; e++) g_expw[b * EV + e] = 0.f;
        g_expw[b * EV + i1] = p[i1];
        g_expw[b * EV + i2] = p[i2];
        atomicOr(&g_used[i1], 1);
        atomicOr(&g_used[i2], 1);
    }
}

// ---------------- fused activations ----------------
__global__ void k_act() {
    int i = blockIdx.x * 256 + threadIdx.x;
    if (i < BV * FDV) {
        g_ffact[i] = gelu_exact(g_ffh1[i]) * g_ffh3[i];
    } else {
        int j = i - BV * FDV;
        if (j < EV * BV * FEV) {
            int e = j >> 13;
            int b = (j >> 10) & 7;
            g_eact[j] = gelu_exact(g_eh1[j]) * g_eh3[j] * g_expw[b * EV + e];
        }
    }
}

// ---------------- launch ----------------
extern "C" void kernel_launch(void* const* d_in, const int* in_sizes, int n_in,
                              void* d_out, int out_size) {
    const float* x    = (const float*)d_in[0];
    const float* mask = (const float*)d_in[1];
    const float* fc   = (const float*)d_in[2];
    const float* fs   = (const float*)d_in[3];
    const float* ck   = (const float*)d_in[4];
    const float* cv   = (const float*)d_in[5];
    const float* wqkv = (const float*)d_in[6];
    const float* wo   = (const float*)d_in[7];
    const float* anw  = (const float*)d_in[8];
    const float* fnw  = (const float*)d_in[9];
    const float* w1   = (const float*)d_in[10];
    const float* w2   = (const float*)d_in[11];
    const float* w3   = (const float*)d_in[12];
    const float* gw   = (const float*)d_in[13];
    const float* m1   = (const float*)d_in[14];
    const float* m2   = (const float*)d_in[15];
    const float* m3   = (const float*)d_in[16];
    const int*   sp   = (const int*)d_in[17];
    float* out = (float*)d_out;

    k_init<<<148, 256>>>(x);                            // 1
    k_rms1<<<8, 512>>>(x, anw);                         // 2
    k_qkv<<<dim3(10, 32), 256>>>(wqkv);                 // 3
    k_attn<<<dim3(NSPLIT, NKV, BV), 256>>>(ck, cv, mask, fc, fs, sp);  // 4
    k_comb<<<64, 256>>>();                              // 5
    k_wo<<<dim3(256, 4), 256>>>(wo);                    // 6  <- ncu -s 5 target
    k_rms2<<<8, 512>>>(fnw, out);                       // 7
    k_gate<<<8, 256>>>(gw);                             // 8
    k_fused13<<<1280, 256>>>(w1, w3, m1, m3);           // 9
    k_act<<<(BV * FDV + EV * BV * FEV + 255) / 256, 256>>>();  // 10
    k_fused2<<<2304, 256>>>(w2, m2, out);               // 11
}